// round 12
// baseline (speedup 1.0000x reference)
#include <cuda_runtime.h>
#include <cuda_fp16.h>
#include <cstdint>

#define N_NODES   50000
#define N_EDGES   800000
#define F         96
#define NF4       (F / 4)          // 24 uint2 per fp16 node row
#define N_CLASSES 10
#define N_GRAPHS  512
#define NF        (N_NODES * F)
#define SCAN_NB   ((N_NODES + 255) / 256)   // 196
#define WS_PITCH  104

// ---------------- scratch (device globals; no allocations allowed) ----------------
__device__ float g_deg[N_NODES];
__device__ float g_dis[N_NODES];
__device__ float g_selfn[N_NODES];
__device__ int   g_gph[N_NODES];
__device__ int   g_cntd[N_NODES];
__device__ int   g_cur[N_NODES];
__device__ int   g_off[N_NODES + 1];
__device__ unsigned long long g_state[256];   // lookback scan state (flag<<32 | value)
__device__ int   g_csr_src[N_EDGES];
__device__ __align__(16) float  g_csr_norm[N_EDGES];
__device__ __align__(16) __half g_xwh[NF];
__device__ __align__(16) float  g_hA[NF];
__device__ __align__(16) float  g_hB[NF];
__device__ float g_pool[N_GRAPHS * F];
__device__ int   g_cnt[N_GRAPHS];
__device__ int   g_ei64, g_b64;

__device__ __forceinline__ float* buf_sel(int s) { return s == 1 ? g_hA : g_hB; }

__device__ __forceinline__ int clampi(long long v, int lim) {
    int r = (int)v;
    if (r < 0) r = 0;
    if (r >= lim) r = lim - 1;
    return r;
}

__device__ __forceinline__ int load_idx(const void* p, long long i, int is64, int lim) {
    long long v = is64 ? ((const long long*)p)[i] : (long long)((const int*)p)[i];
    return clampi(v, lim);
}

__device__ __forceinline__ unsigned f2tf32(float x) {
    unsigned u;
    asm("cvt.rna.tf32.f32 %0, %1;" : "=r"(u) : "f"(x));
    return u;
}

// ---------------- init + dtype detection -------------------------------------------
__global__ void k_init(const void* ei, const void* bt) {
    int i = blockIdx.x * blockDim.x + threadIdx.x;
    if (i < N_NODES) { g_deg[i] = 1.0f; g_cntd[i] = 0; g_cur[i] = 0; }
    if (i < N_GRAPHS * F)  g_pool[i] = 0.0f;
    if (i < N_GRAPHS)      g_cnt[i] = 0;
    if (i < 256)           g_state[i] = 0ULL;
    if (i == 0) {
        const unsigned long long* p = (const unsigned long long*)ei;
        int is64 = 1;
        for (int k = 0; k < 512; k++)
            if (p[k] >= (1ULL << 32)) { is64 = 0; break; }
        g_ei64 = is64;
        const unsigned long long* q = (const unsigned long long*)bt;
        int b64 = 1;
        for (int k = 0; k < 512; k++)
            if (q[k] >= (1ULL << 32)) { b64 = 0; break; }
        g_b64 = b64;
    }
}

// ---------------- prep: weighted degree + dst counts (2 edges/thread) --------------
__global__ void k_prep(const void* __restrict__ ei, const float* __restrict__ w) {
    int e = (blockIdx.x * blockDim.x + threadIdx.x) * 2;
    if (e >= N_EDGES) return;
    int is64 = g_ei64;
    int d0, d1;
    if (is64) {
        longlong2 dd = *(const longlong2*)((const long long*)ei + N_EDGES + e);
        d0 = clampi(dd.x, N_NODES); d1 = clampi(dd.y, N_NODES);
    } else {
        int2 dd = *(const int2*)((const int*)ei + N_EDGES + e);
        d0 = clampi(dd.x, N_NODES); d1 = clampi(dd.y, N_NODES);
    }
    float2 wv = *(const float2*)(w + e);
    atomicAdd(&g_deg[d0], wv.x);
    atomicAdd(&g_deg[d1], wv.y);
    atomicAdd(&g_cntd[d0], 1);
    atomicAdd(&g_cntd[d1], 1);
}

// ---------------- fused: dis/selfn/batch + single-pass lookback scan ---------------
__global__ void k_scan(const void* __restrict__ batch) {
    __shared__ int sm[256];
    __shared__ int s_prefix;
    int b = blockIdx.x, t = threadIdx.x;
    int i = b * 256 + t;

    if (i < N_NODES) {
        float dg  = g_deg[i];
        float dis = dg > 0.0f ? rsqrtf(dg) : 0.0f;
        g_dis[i]   = dis;
        g_selfn[i] = dis * dis;
        int gph = load_idx(batch, i, g_b64, N_GRAPHS);
        g_gph[i] = gph;
        unsigned active = __activemask();
        unsigned mask = __match_any_sync(active, gph);
        int leader = __ffs(mask) - 1;
        if ((t & 31) == leader) atomicAdd(&g_cnt[gph], __popc(mask));
    }

    int v = (i < N_NODES) ? g_cntd[i] : 0;
    sm[t] = v; __syncthreads();
    for (int ofs = 1; ofs < 256; ofs <<= 1) {
        int add = (t >= ofs) ? sm[t - ofs] : 0;
        __syncthreads();
        sm[t] += add;
        __syncthreads();
    }
    int total = sm[255];

    if (t == 0) {
        int prefix = 0;
        if (b == 0) {
            atomicExch(&g_state[0], (2ULL << 32) | (unsigned)total);
        } else {
            atomicExch(&g_state[b], (1ULL << 32) | (unsigned)total);  // aggregate
            int j = b - 1;
            while (j >= 0) {
                unsigned long long s;
                do { s = atomicAdd(&g_state[j], 0ULL); } while ((s >> 32) == 0ULL);
                prefix += (int)(unsigned)s;
                if ((s >> 32) == 2ULL) break;   // inclusive found
                j--;
            }
            atomicExch(&g_state[b], (2ULL << 32) | (unsigned)(prefix + total));
        }
        s_prefix = prefix;
    }
    __syncthreads();

    if (i < N_NODES) g_off[i] = s_prefix + sm[t] - v;
    if (i == 0) g_off[N_NODES] = N_EDGES;
}

// ---------------- fill CSR (2 edges/thread) ----------------------------------------
__global__ void k_fill(const void* __restrict__ ei, const float* __restrict__ w) {
    int e = (blockIdx.x * blockDim.x + threadIdx.x) * 2;
    if (e >= N_EDGES) return;
    int is64 = g_ei64;
    int s0, s1, d0, d1;
    if (is64) {
        longlong2 ss = *(const longlong2*)((const long long*)ei + e);
        longlong2 dd = *(const longlong2*)((const long long*)ei + N_EDGES + e);
        s0 = clampi(ss.x, N_NODES); s1 = clampi(ss.y, N_NODES);
        d0 = clampi(dd.x, N_NODES); d1 = clampi(dd.y, N_NODES);
    } else {
        int2 ss = *(const int2*)((const int*)ei + e);
        int2 dd = *(const int2*)((const int*)ei + N_EDGES + e);
        s0 = clampi(ss.x, N_NODES); s1 = clampi(ss.y, N_NODES);
        d0 = clampi(dd.x, N_NODES); d1 = clampi(dd.y, N_NODES);
    }
    float2 wv = *(const float2*)(w + e);
    int slot0 = g_off[d0] + atomicAdd(&g_cur[d0], 1);
    g_csr_src[slot0]  = s0;
    g_csr_norm[slot0] = g_dis[s0] * wv.x * g_dis[d0];
    int slot1 = g_off[d1] + atomicAdd(&g_cur[d1], 1);
    g_csr_src[slot1]  = s1;
    g_csr_norm[slot1] = g_dis[s1] * wv.y * g_dis[d1];
}

// ---------------- GEMM (tensor path): g_xwh = A @ W, tf32 mma, fp32 accum ----------
__global__ void k_gemm(const float* __restrict__ Aext, int asel,
                       const float* __restrict__ W) {
    __shared__ unsigned ws[96 * WS_PITCH];
    const float* A = (asel == 0) ? Aext : (asel == 1 ? g_hA : g_hB);

    int tid = threadIdx.x;
    for (int idx = tid; idx < 96 * 96; idx += 256) {
        int k = idx / 96, n = idx - k * 96;
        ws[k * WS_PITCH + n] = f2tf32(W[idx]);
    }
    __syncthreads();

    int lane = tid & 31, warp = tid >> 5;
    int r0 = blockIdx.x * 128 + warp * 16;
    int qr = lane >> 2;
    int qc = lane & 3;

    float acc[12][4];
#pragma unroll
    for (int n = 0; n < 12; n++)
#pragma unroll
        for (int j = 0; j < 4; j++) acc[n][j] = 0.0f;

    int row_lo = r0 + qr;
    int row_hi = row_lo + 8;
    int rl = row_lo < N_NODES ? row_lo : N_NODES - 1;
    int rh = row_hi < N_NODES ? row_hi : N_NODES - 1;

#pragma unroll
    for (int k0 = 0; k0 < 96; k0 += 8) {
        unsigned a0 = f2tf32(A[(size_t)rl * 96 + k0 + qc]);
        unsigned a1 = f2tf32(A[(size_t)rh * 96 + k0 + qc]);
        unsigned a2 = f2tf32(A[(size_t)rl * 96 + k0 + qc + 4]);
        unsigned a3 = f2tf32(A[(size_t)rh * 96 + k0 + qc + 4]);
#pragma unroll
        for (int n = 0; n < 12; n++) {
            unsigned b0 = ws[(k0 + qc) * WS_PITCH + n * 8 + qr];
            unsigned b1 = ws[(k0 + 4 + qc) * WS_PITCH + n * 8 + qr];
            asm volatile(
                "mma.sync.aligned.m16n8k8.row.col.f32.tf32.tf32.f32 "
                "{%0,%1,%2,%3}, {%4,%5,%6,%7}, {%8,%9}, {%0,%1,%2,%3};"
                : "+f"(acc[n][0]), "+f"(acc[n][1]), "+f"(acc[n][2]), "+f"(acc[n][3])
                : "r"(a0), "r"(a1), "r"(a2), "r"(a3), "r"(b0), "r"(b1));
        }
    }

    int colb = qc * 2;
#pragma unroll
    for (int n = 0; n < 12; n++) {
        int col = n * 8 + colb;
        if (row_lo < N_NODES)
            *(__half2*)&g_xwh[(size_t)row_lo * 96 + col] = __floats2half2_rn(acc[n][0], acc[n][1]);
        if (row_hi < N_NODES)
            *(__half2*)&g_xwh[(size_t)row_hi * 96 + col] = __floats2half2_rn(acc[n][2], acc[n][3]);
    }
}

// ---------------- fused gather: CSR aggregate + self-loop + bias (+relu) (+pool) ---
__global__ void k_gather(int osel, const float* __restrict__ bias, int relu, int do_pool) {
    int warp = (blockIdx.x * blockDim.x + threadIdx.x) >> 5;
    int lane = threadIdx.x & 31;
    if (warp >= N_NODES || lane >= NF4) return;
    float* out = buf_sel(osel);
    const uint2* __restrict__ xwu = (const uint2*)g_xwh;

    int beg = __ldg(&g_off[warp]), end = __ldg(&g_off[warp + 1]);
    float4 acc = make_float4(0.f, 0.f, 0.f, 0.f);
    int i = beg;
    for (; i + 3 < end; i += 4) {
        int   s0 = __ldg(&g_csr_src[i]),      s1 = __ldg(&g_csr_src[i + 1]);
        int   s2 = __ldg(&g_csr_src[i + 2]),  s3 = __ldg(&g_csr_src[i + 3]);
        float n0 = __ldg(&g_csr_norm[i]),     n1 = __ldg(&g_csr_norm[i + 1]);
        float n2 = __ldg(&g_csr_norm[i + 2]), n3 = __ldg(&g_csr_norm[i + 3]);
        uint2 u0 = xwu[(size_t)s0 * NF4 + lane];
        uint2 u1 = xwu[(size_t)s1 * NF4 + lane];
        uint2 u2 = xwu[(size_t)s2 * NF4 + lane];
        uint2 u3 = xwu[(size_t)s3 * NF4 + lane];
        float2 lo0 = __half22float2(*(__half2*)&u0.x), hi0 = __half22float2(*(__half2*)&u0.y);
        float2 lo1 = __half22float2(*(__half2*)&u1.x), hi1 = __half22float2(*(__half2*)&u1.y);
        float2 lo2 = __half22float2(*(__half2*)&u2.x), hi2 = __half22float2(*(__half2*)&u2.y);
        float2 lo3 = __half22float2(*(__half2*)&u3.x), hi3 = __half22float2(*(__half2*)&u3.y);
        acc.x = fmaf(n0, lo0.x, acc.x); acc.y = fmaf(n0, lo0.y, acc.y);
        acc.z = fmaf(n0, hi0.x, acc.z); acc.w = fmaf(n0, hi0.y, acc.w);
        acc.x = fmaf(n1, lo1.x, acc.x); acc.y = fmaf(n1, lo1.y, acc.y);
        acc.z = fmaf(n1, hi1.x, acc.z); acc.w = fmaf(n1, hi1.y, acc.w);
        acc.x = fmaf(n2, lo2.x, acc.x); acc.y = fmaf(n2, lo2.y, acc.y);
        acc.z = fmaf(n2, hi2.x, acc.z); acc.w = fmaf(n2, hi2.y, acc.w);
        acc.x = fmaf(n3, lo3.x, acc.x); acc.y = fmaf(n3, lo3.y, acc.y);
        acc.z = fmaf(n3, hi3.x, acc.z); acc.w = fmaf(n3, hi3.y, acc.w);
    }
    for (; i < end; i++) {
        int   s0 = __ldg(&g_csr_src[i]);
        float n0 = __ldg(&g_csr_norm[i]);
        uint2 u0 = xwu[(size_t)s0 * NF4 + lane];
        float2 lo0 = __half22float2(*(__half2*)&u0.x), hi0 = __half22float2(*(__half2*)&u0.y);
        acc.x = fmaf(n0, lo0.x, acc.x); acc.y = fmaf(n0, lo0.y, acc.y);
        acc.z = fmaf(n0, hi0.x, acc.z); acc.w = fmaf(n0, hi0.y, acc.w);
    }
    {
        float sn = g_selfn[warp];
        uint2 u = xwu[(size_t)warp * NF4 + lane];
        float2 lo = __half22float2(*(__half2*)&u.x), hi = __half22float2(*(__half2*)&u.y);
        acc.x = fmaf(sn, lo.x, acc.x); acc.y = fmaf(sn, lo.y, acc.y);
        acc.z = fmaf(sn, hi.x, acc.z); acc.w = fmaf(sn, hi.y, acc.w);
    }
    float4 bv = ((const float4*)bias)[lane];
    acc.x += bv.x; acc.y += bv.y; acc.z += bv.z; acc.w += bv.w;
    if (relu) {
        acc.x = fmaxf(acc.x, 0.f); acc.y = fmaxf(acc.y, 0.f);
        acc.z = fmaxf(acc.z, 0.f); acc.w = fmaxf(acc.w, 0.f);
    }
    ((float4*)out)[(size_t)warp * NF4 + lane] = acc;

    if (do_pool) {
        int gph = g_gph[warp];
        float* pp = &g_pool[gph * F + lane * 4];
        atomicAdd(pp + 0, acc.x);
        atomicAdd(pp + 1, acc.y);
        atomicAdd(pp + 2, acc.z);
        atomicAdd(pp + 3, acc.w);
    }
}

// ---------------- head ------------------------------------------------------------
__global__ void k_final(const float* __restrict__ Wl, const float* __restrict__ bl,
                        float* __restrict__ out) {
    int t = blockIdx.x * blockDim.x + threadIdx.x;
    if (t >= N_GRAPHS * N_CLASSES) return;
    int gph = t / N_CLASSES;
    int c = t - gph * N_CLASSES;
    float inv = 1.0f / fmaxf((float)g_cnt[gph], 1.0f);
    float s = 0.0f;
#pragma unroll 8
    for (int k = 0; k < 96; k++)
        s = fmaf(g_pool[gph * 96 + k], Wl[k * N_CLASSES + c], s);
    out[t] = s * inv + bl[c];
}

// ===================================================================================
extern "C" void kernel_launch(void* const* d_in, const int* in_sizes, int n_in,
                              void* d_out, int out_size) {
    int ix = 0, iew = 1, iWl = 8, ibl = 9, iei = 10, ibatch = 11;
    int iW[3] = {2, 4, 6}, iB[3] = {3, 5, 7};
    {
        int tW[3], tB[3], nw = 0, nb = 0;
        int tx = -1, tew = -1, twl = -1, tbl = -1, tei = -1, tbt = -1;
        for (int i = 0; i < n_in; i++) {
            switch (in_sizes[i]) {
                case N_NODES * F:      tx  = i; break;
                case N_EDGES:          tew = i; break;
                case F * F:            if (nw < 3) tW[nw++] = i; break;
                case F:                if (nb < 3) tB[nb++] = i; break;
                case F * N_CLASSES:    twl = i; break;
                case N_CLASSES:        tbl = i; break;
                case 2 * N_EDGES:      tei = i; break;
                case N_NODES:          tbt = i; break;
                default: break;
            }
        }
        if (tx >= 0 && tew >= 0 && nw == 3 && nb == 3 && twl >= 0 && tbl >= 0 &&
            tei >= 0 && tbt >= 0) {
            ix = tx; iew = tew; iWl = twl; ibl = tbl; iei = tei; ibatch = tbt;
            for (int j = 0; j < 3; j++) { iW[j] = tW[j]; iB[j] = tB[j]; }
        }
    }

    const float* x     = (const float*)d_in[ix];
    const float* ew    = (const float*)d_in[iew];
    const float* W1    = (const float*)d_in[iW[0]];
    const float* b1    = (const float*)d_in[iB[0]];
    const float* W2    = (const float*)d_in[iW[1]];
    const float* b2    = (const float*)d_in[iB[1]];
    const float* W3    = (const float*)d_in[iW[2]];
    const float* b3    = (const float*)d_in[iB[2]];
    const float* Wl    = (const float*)d_in[iWl];
    const float* bl    = (const float*)d_in[ibl];
    const void*  ei    = d_in[iei];
    const void*  batch = d_in[ibatch];
    float* out = (float*)d_out;

    const int T = 256;
    const int node_grid  = (N_NODES + T - 1) / T;
    const int edge2_grid = (N_EDGES / 2 + T - 1) / T;

    k_init<<<node_grid, T>>>(ei, batch);
    k_prep<<<edge2_grid, T>>>(ei, ew);
    k_scan<<<SCAN_NB, 256>>>(batch);
    k_fill<<<edge2_grid, T>>>(ei, ew);

    const int gemm_grid   = (N_NODES + 127) / 128;
    const int gather_grid = (N_NODES * 32 + T - 1) / T;

    k_gemm<<<gemm_grid, T>>>(x, 0, W1);
    k_gather<<<gather_grid, T>>>(1, b1, 1, 0);

    k_gemm<<<gemm_grid, T>>>(nullptr, 1, W2);
    k_gather<<<gather_grid, T>>>(2, b2, 1, 0);

    k_gemm<<<gemm_grid, T>>>(nullptr, 2, W3);
    k_gather<<<gather_grid, T>>>(1, b3, 0, 1);

    k_final<<<(N_GRAPHS * N_CLASSES + T - 1) / T, T>>>(Wl, bl, out);
}

// round 13
// speedup vs baseline: 1.0107x; 1.0107x over previous
#include <cuda_runtime.h>
#include <cuda_fp16.h>
#include <cstdint>

#define N_NODES   50000
#define N_EDGES   800000
#define F         96
#define NF4       (F / 4)          // 24 uint2 per fp16 node row
#define N_CLASSES 10
#define N_GRAPHS  512
#define NF        (N_NODES * F)
#define SCAN_NB   ((N_NODES + 255) / 256)   // 196
#define WS_PITCH  104

// ---------------- scratch (device globals; no allocations allowed) ----------------
__device__ float g_deg[N_NODES];
__device__ float g_dis[N_NODES];
__device__ float g_selfn[N_NODES];
__device__ int   g_gph[N_NODES];
__device__ int   g_cntd[N_NODES];
__device__ int   g_cur[N_NODES];
__device__ int   g_off[N_NODES + 1];
__device__ int   g_part[256];
__device__ __align__(16) uint2  g_csr[N_EDGES];     // packed {src, norm-bits}
__device__ __align__(16) __half g_xwh[NF];
__device__ __align__(16) float  g_hA[NF];
__device__ __align__(16) float  g_hB[NF];
__device__ float g_pool[N_GRAPHS * F];
__device__ int   g_cnt[N_GRAPHS];
__device__ int   g_ei64, g_b64;

__device__ __forceinline__ float* buf_sel(int s) { return s == 1 ? g_hA : g_hB; }

__device__ __forceinline__ int clampi(long long v, int lim) {
    int r = (int)v;
    if (r < 0) r = 0;
    if (r >= lim) r = lim - 1;
    return r;
}

__device__ __forceinline__ int load_idx(const void* p, long long i, int is64, int lim) {
    long long v = is64 ? ((const long long*)p)[i] : (long long)((const int*)p)[i];
    return clampi(v, lim);
}

__device__ __forceinline__ unsigned f2tf32(float x) {
    unsigned u;
    asm("cvt.rna.tf32.f32 %0, %1;" : "=r"(u) : "f"(x));
    return u;
}

// ---------------- init + dtype detection -------------------------------------------
__global__ void k_init(const void* ei, const void* bt) {
    int i = blockIdx.x * blockDim.x + threadIdx.x;
    if (i < N_NODES) { g_deg[i] = 1.0f; g_cntd[i] = 0; g_cur[i] = 0; }
    if (i < N_GRAPHS * F)  g_pool[i] = 0.0f;
    if (i < N_GRAPHS)      g_cnt[i] = 0;
    if (i == 0) {
        const unsigned long long* p = (const unsigned long long*)ei;
        int is64 = 1;
        for (int k = 0; k < 512; k++)
            if (p[k] >= (1ULL << 32)) { is64 = 0; break; }
        g_ei64 = is64;
        const unsigned long long* q = (const unsigned long long*)bt;
        int b64 = 1;
        for (int k = 0; k < 512; k++)
            if (q[k] >= (1ULL << 32)) { b64 = 0; break; }
        g_b64 = b64;
    }
}

// ---------------- prep: weighted degree + dst counts (2 edges/thread) --------------
__global__ void k_prep(const void* __restrict__ ei, const float* __restrict__ w) {
    int e = (blockIdx.x * blockDim.x + threadIdx.x) * 2;
    if (e >= N_EDGES) return;
    int is64 = g_ei64;
    int d0, d1;
    if (is64) {
        longlong2 dd = *(const longlong2*)((const long long*)ei + N_EDGES + e);
        d0 = clampi(dd.x, N_NODES); d1 = clampi(dd.y, N_NODES);
    } else {
        int2 dd = *(const int2*)((const int*)ei + N_EDGES + e);
        d0 = clampi(dd.x, N_NODES); d1 = clampi(dd.y, N_NODES);
    }
    float2 wv = *(const float2*)(w + e);
    atomicAdd(&g_deg[d0], wv.x);
    atomicAdd(&g_deg[d1], wv.y);
    atomicAdd(&g_cntd[d0], 1);
    atomicAdd(&g_cntd[d1], 1);
}

// ---------------- scan1: dis/selfn/batch + block-local scan (round-11 proven) ------
__global__ void k_scan1(const void* __restrict__ batch) {
    __shared__ int sm[256];
    int b = blockIdx.x, t = threadIdx.x;
    int i = b * 256 + t;

    if (i < N_NODES) {
        float dg  = g_deg[i];
        float dis = dg > 0.0f ? rsqrtf(dg) : 0.0f;
        g_dis[i]   = dis;
        g_selfn[i] = dis * dis;
        int gph = load_idx(batch, i, g_b64, N_GRAPHS);
        g_gph[i] = gph;
        unsigned active = __activemask();
        unsigned mask = __match_any_sync(active, gph);
        int leader = __ffs(mask) - 1;
        if ((t & 31) == leader) atomicAdd(&g_cnt[gph], __popc(mask));
    }

    int v = (i < N_NODES) ? g_cntd[i] : 0;
    sm[t] = v; __syncthreads();
    for (int ofs = 1; ofs < 256; ofs <<= 1) {
        int add = (t >= ofs) ? sm[t - ofs] : 0;
        __syncthreads();
        sm[t] += add;
        __syncthreads();
    }
    if (i < N_NODES) g_off[i] = sm[t] - v;
    if (t == 255) g_part[b] = sm[255];
}

// ---------------- scan3: per-block prefix of partials + offset finalize ------------
__global__ void k_scan3() {
    __shared__ int sbase;
    int b = blockIdx.x, t = threadIdx.x;
    if (t < 32) {
        int s = 0;
        for (int j = t; j < b; j += 32) s += g_part[j];
#pragma unroll
        for (int o = 16; o > 0; o >>= 1) s += __shfl_down_sync(0xffffffff, s, o);
        if (t == 0) sbase = s;
    }
    __syncthreads();
    int i = b * 256 + t;
    if (i < N_NODES) g_off[i] += sbase;
    if (i == 0) g_off[N_NODES] = N_EDGES;
}

// ---------------- fill CSR (2 edges/thread, packed 8B entries) ---------------------
__global__ void k_fill(const void* __restrict__ ei, const float* __restrict__ w) {
    int e = (blockIdx.x * blockDim.x + threadIdx.x) * 2;
    if (e >= N_EDGES) return;
    int is64 = g_ei64;
    int s0, s1, d0, d1;
    if (is64) {
        longlong2 ss = *(const longlong2*)((const long long*)ei + e);
        longlong2 dd = *(const longlong2*)((const long long*)ei + N_EDGES + e);
        s0 = clampi(ss.x, N_NODES); s1 = clampi(ss.y, N_NODES);
        d0 = clampi(dd.x, N_NODES); d1 = clampi(dd.y, N_NODES);
    } else {
        int2 ss = *(const int2*)((const int*)ei + e);
        int2 dd = *(const int2*)((const int*)ei + N_EDGES + e);
        s0 = clampi(ss.x, N_NODES); s1 = clampi(ss.y, N_NODES);
        d0 = clampi(dd.x, N_NODES); d1 = clampi(dd.y, N_NODES);
    }
    float2 wv = *(const float2*)(w + e);
    int slot0 = g_off[d0] + atomicAdd(&g_cur[d0], 1);
    uint2 c0;
    c0.x = (unsigned)s0;
    c0.y = __float_as_uint(g_dis[s0] * wv.x * g_dis[d0]);
    g_csr[slot0] = c0;
    int slot1 = g_off[d1] + atomicAdd(&g_cur[d1], 1);
    uint2 c1;
    c1.x = (unsigned)s1;
    c1.y = __float_as_uint(g_dis[s1] * wv.y * g_dis[d1]);
    g_csr[slot1] = c1;
}

// ---------------- GEMM (tensor path): g_xwh = A @ W, tf32 mma, fp32 accum ----------
__global__ void k_gemm(const float* __restrict__ Aext, int asel,
                       const float* __restrict__ W) {
    __shared__ unsigned ws[96 * WS_PITCH];
    const float* A = (asel == 0) ? Aext : (asel == 1 ? g_hA : g_hB);

    int tid = threadIdx.x;
    for (int idx = tid; idx < 96 * 96; idx += 256) {
        int k = idx / 96, n = idx - k * 96;
        ws[k * WS_PITCH + n] = f2tf32(W[idx]);
    }
    __syncthreads();

    int lane = tid & 31, warp = tid >> 5;
    int r0 = blockIdx.x * 128 + warp * 16;
    int qr = lane >> 2;
    int qc = lane & 3;

    float acc[12][4];
#pragma unroll
    for (int n = 0; n < 12; n++)
#pragma unroll
        for (int j = 0; j < 4; j++) acc[n][j] = 0.0f;

    int row_lo = r0 + qr;
    int row_hi = row_lo + 8;
    int rl = row_lo < N_NODES ? row_lo : N_NODES - 1;
    int rh = row_hi < N_NODES ? row_hi : N_NODES - 1;

#pragma unroll
    for (int k0 = 0; k0 < 96; k0 += 8) {
        unsigned a0 = f2tf32(A[(size_t)rl * 96 + k0 + qc]);
        unsigned a1 = f2tf32(A[(size_t)rh * 96 + k0 + qc]);
        unsigned a2 = f2tf32(A[(size_t)rl * 96 + k0 + qc + 4]);
        unsigned a3 = f2tf32(A[(size_t)rh * 96 + k0 + qc + 4]);
#pragma unroll
        for (int n = 0; n < 12; n++) {
            unsigned b0 = ws[(k0 + qc) * WS_PITCH + n * 8 + qr];
            unsigned b1 = ws[(k0 + 4 + qc) * WS_PITCH + n * 8 + qr];
            asm volatile(
                "mma.sync.aligned.m16n8k8.row.col.f32.tf32.tf32.f32 "
                "{%0,%1,%2,%3}, {%4,%5,%6,%7}, {%8,%9}, {%0,%1,%2,%3};"
                : "+f"(acc[n][0]), "+f"(acc[n][1]), "+f"(acc[n][2]), "+f"(acc[n][3])
                : "r"(a0), "r"(a1), "r"(a2), "r"(a3), "r"(b0), "r"(b1));
        }
    }

    int colb = qc * 2;
#pragma unroll
    for (int n = 0; n < 12; n++) {
        int col = n * 8 + colb;
        if (row_lo < N_NODES)
            *(__half2*)&g_xwh[(size_t)row_lo * 96 + col] = __floats2half2_rn(acc[n][0], acc[n][1]);
        if (row_hi < N_NODES)
            *(__half2*)&g_xwh[(size_t)row_hi * 96 + col] = __floats2half2_rn(acc[n][2], acc[n][3]);
    }
}

// ---------------- fused gather: CSR aggregate + self-loop + bias (+relu) (+pool) ---
__global__ void k_gather(int osel, const float* __restrict__ bias, int relu, int do_pool) {
    int warp = (blockIdx.x * blockDim.x + threadIdx.x) >> 5;
    int lane = threadIdx.x & 31;
    if (warp >= N_NODES || lane >= NF4) return;
    float* out = buf_sel(osel);
    const uint2* __restrict__ xwu = (const uint2*)g_xwh;

    int beg = __ldg(&g_off[warp]), end = __ldg(&g_off[warp + 1]);
    float4 acc = make_float4(0.f, 0.f, 0.f, 0.f);
    int i = beg;
    for (; i + 3 < end; i += 4) {
        uint2 c0 = __ldg(&g_csr[i]);
        uint2 c1 = __ldg(&g_csr[i + 1]);
        uint2 c2 = __ldg(&g_csr[i + 2]);
        uint2 c3 = __ldg(&g_csr[i + 3]);
        float n0 = __uint_as_float(c0.y), n1 = __uint_as_float(c1.y);
        float n2 = __uint_as_float(c2.y), n3 = __uint_as_float(c3.y);
        uint2 u0 = xwu[(size_t)c0.x * NF4 + lane];
        uint2 u1 = xwu[(size_t)c1.x * NF4 + lane];
        uint2 u2 = xwu[(size_t)c2.x * NF4 + lane];
        uint2 u3 = xwu[(size_t)c3.x * NF4 + lane];
        float2 lo0 = __half22float2(*(__half2*)&u0.x), hi0 = __half22float2(*(__half2*)&u0.y);
        float2 lo1 = __half22float2(*(__half2*)&u1.x), hi1 = __half22float2(*(__half2*)&u1.y);
        float2 lo2 = __half22float2(*(__half2*)&u2.x), hi2 = __half22float2(*(__half2*)&u2.y);
        float2 lo3 = __half22float2(*(__half2*)&u3.x), hi3 = __half22float2(*(__half2*)&u3.y);
        acc.x = fmaf(n0, lo0.x, acc.x); acc.y = fmaf(n0, lo0.y, acc.y);
        acc.z = fmaf(n0, hi0.x, acc.z); acc.w = fmaf(n0, hi0.y, acc.w);
        acc.x = fmaf(n1, lo1.x, acc.x); acc.y = fmaf(n1, lo1.y, acc.y);
        acc.z = fmaf(n1, hi1.x, acc.z); acc.w = fmaf(n1, hi1.y, acc.w);
        acc.x = fmaf(n2, lo2.x, acc.x); acc.y = fmaf(n2, lo2.y, acc.y);
        acc.z = fmaf(n2, hi2.x, acc.z); acc.w = fmaf(n2, hi2.y, acc.w);
        acc.x = fmaf(n3, lo3.x, acc.x); acc.y = fmaf(n3, lo3.y, acc.y);
        acc.z = fmaf(n3, hi3.x, acc.z); acc.w = fmaf(n3, hi3.y, acc.w);
    }
    for (; i < end; i++) {
        uint2 c0 = __ldg(&g_csr[i]);
        float n0 = __uint_as_float(c0.y);
        uint2 u0 = xwu[(size_t)c0.x * NF4 + lane];
        float2 lo0 = __half22float2(*(__half2*)&u0.x), hi0 = __half22float2(*(__half2*)&u0.y);
        acc.x = fmaf(n0, lo0.x, acc.x); acc.y = fmaf(n0, lo0.y, acc.y);
        acc.z = fmaf(n0, hi0.x, acc.z); acc.w = fmaf(n0, hi0.y, acc.w);
    }
    {
        float sn = g_selfn[warp];
        uint2 u = xwu[(size_t)warp * NF4 + lane];
        float2 lo = __half22float2(*(__half2*)&u.x), hi = __half22float2(*(__half2*)&u.y);
        acc.x = fmaf(sn, lo.x, acc.x); acc.y = fmaf(sn, lo.y, acc.y);
        acc.z = fmaf(sn, hi.x, acc.z); acc.w = fmaf(sn, hi.y, acc.w);
    }
    float4 bv = ((const float4*)bias)[lane];
    acc.x += bv.x; acc.y += bv.y; acc.z += bv.z; acc.w += bv.w;
    if (relu) {
        acc.x = fmaxf(acc.x, 0.f); acc.y = fmaxf(acc.y, 0.f);
        acc.z = fmaxf(acc.z, 0.f); acc.w = fmaxf(acc.w, 0.f);
    }
    ((float4*)out)[(size_t)warp * NF4 + lane] = acc;

    if (do_pool) {
        int gph = g_gph[warp];
        float* pp = &g_pool[gph * F + lane * 4];
        atomicAdd(pp + 0, acc.x);
        atomicAdd(pp + 1, acc.y);
        atomicAdd(pp + 2, acc.z);
        atomicAdd(pp + 3, acc.w);
    }
}

// ---------------- head ------------------------------------------------------------
__global__ void k_final(const float* __restrict__ Wl, const float* __restrict__ bl,
                        float* __restrict__ out) {
    int t = blockIdx.x * blockDim.x + threadIdx.x;
    if (t >= N_GRAPHS * N_CLASSES) return;
    int gph = t / N_CLASSES;
    int c = t - gph * N_CLASSES;
    float inv = 1.0f / fmaxf((float)g_cnt[gph], 1.0f);
    float s = 0.0f;
#pragma unroll 8
    for (int k = 0; k < 96; k++)
        s = fmaf(g_pool[gph * 96 + k], Wl[k * N_CLASSES + c], s);
    out[t] = s * inv + bl[c];
}

// ===================================================================================
extern "C" void kernel_launch(void* const* d_in, const int* in_sizes, int n_in,
                              void* d_out, int out_size) {
    int ix = 0, iew = 1, iWl = 8, ibl = 9, iei = 10, ibatch = 11;
    int iW[3] = {2, 4, 6}, iB[3] = {3, 5, 7};
    {
        int tW[3], tB[3], nw = 0, nb = 0;
        int tx = -1, tew = -1, twl = -1, tbl = -1, tei = -1, tbt = -1;
        for (int i = 0; i < n_in; i++) {
            switch (in_sizes[i]) {
                case N_NODES * F:      tx  = i; break;
                case N_EDGES:          tew = i; break;
                case F * F:            if (nw < 3) tW[nw++] = i; break;
                case F:                if (nb < 3) tB[nb++] = i; break;
                case F * N_CLASSES:    twl = i; break;
                case N_CLASSES:        tbl = i; break;
                case 2 * N_EDGES:      tei = i; break;
                case N_NODES:          tbt = i; break;
                default: break;
            }
        }
        if (tx >= 0 && tew >= 0 && nw == 3 && nb == 3 && twl >= 0 && tbl >= 0 &&
            tei >= 0 && tbt >= 0) {
            ix = tx; iew = tew; iWl = twl; ibl = tbl; iei = tei; ibatch = tbt;
            for (int j = 0; j < 3; j++) { iW[j] = tW[j]; iB[j] = tB[j]; }
        }
    }

    const float* x     = (const float*)d_in[ix];
    const float* ew    = (const float*)d_in[iew];
    const float* W1    = (const float*)d_in[iW[0]];
    const float* b1    = (const float*)d_in[iB[0]];
    const float* W2    = (const float*)d_in[iW[1]];
    const float* b2    = (const float*)d_in[iB[1]];
    const float* W3    = (const float*)d_in[iW[2]];
    const float* b3    = (const float*)d_in[iB[2]];
    const float* Wl    = (const float*)d_in[iWl];
    const float* bl    = (const float*)d_in[ibl];
    const void*  ei    = d_in[iei];
    const void*  batch = d_in[ibatch];
    float* out = (float*)d_out;

    const int T = 256;
    const int node_grid  = (N_NODES + T - 1) / T;
    const int edge2_grid = (N_EDGES / 2 + T - 1) / T;

    k_init<<<node_grid, T>>>(ei, batch);
    k_prep<<<edge2_grid, T>>>(ei, ew);
    k_scan1<<<SCAN_NB, 256>>>(batch);
    k_scan3<<<SCAN_NB, 256>>>();
    k_fill<<<edge2_grid, T>>>(ei, ew);

    const int gemm_grid   = (N_NODES + 127) / 128;
    const int gather_grid = (N_NODES * 32 + T - 1) / T;

    k_gemm<<<gemm_grid, T>>>(x, 0, W1);
    k_gather<<<gather_grid, T>>>(1, b1, 1, 0);

    k_gemm<<<gemm_grid, T>>>(nullptr, 1, W2);
    k_gather<<<gather_grid, T>>>(2, b2, 1, 0);

    k_gemm<<<gemm_grid, T>>>(nullptr, 2, W3);
    k_gather<<<gather_grid, T>>>(1, b3, 0, 1);

    k_final<<<(N_GRAPHS * N_CLASSES + T - 1) / T, T>>>(Wl, bl, out);
}

// round 14
// speedup vs baseline: 1.1009x; 1.0892x over previous
#include <cuda_runtime.h>
#include <cuda_fp16.h>
#include <cstdint>

#define N_NODES   50000
#define N_EDGES   800000
#define F         96
#define NF4       (F / 4)          // 24 uint2 per fp16 node row
#define N_CLASSES 10
#define N_GRAPHS  512
#define NF        (N_NODES * F)
#define SCAN_NB   ((N_NODES + 255) / 256)   // 196
#define WS_PITCH  104
#define FIXSCALE  1048576.0f        // 2^20 fixed-point scale for weight sums

// ---------------- scratch (device globals; no allocations allowed) ----------------
__device__ unsigned long long g_dc[N_NODES];   // packed: count<<40 | fixed(deg sum)
__device__ float g_dis[N_NODES];
__device__ float g_selfn[N_NODES];
__device__ int   g_gph[N_NODES];
__device__ int   g_cur[N_NODES];
__device__ int   g_off[N_NODES + 1];
__device__ int   g_part[256];
__device__ __align__(16) uint2  g_csr[N_EDGES];     // packed {src, norm-bits}
__device__ __align__(16) __half g_xwh[NF];
__device__ __align__(16) float  g_hA[NF];
__device__ __align__(16) float  g_hB[NF];
__device__ float g_pool[N_GRAPHS * F];
__device__ int   g_cnt[N_GRAPHS];
__device__ int   g_ei64, g_b64;

__device__ __forceinline__ float* buf_sel(int s) { return s == 1 ? g_hA : g_hB; }

__device__ __forceinline__ int clampi(long long v, int lim) {
    int r = (int)v;
    if (r < 0) r = 0;
    if (r >= lim) r = lim - 1;
    return r;
}

__device__ __forceinline__ int load_idx(const void* p, long long i, int is64, int lim) {
    long long v = is64 ? ((const long long*)p)[i] : (long long)((const int*)p)[i];
    return clampi(v, lim);
}

__device__ __forceinline__ unsigned f2tf32(float x) {
    unsigned u;
    asm("cvt.rna.tf32.f32 %0, %1;" : "=r"(u) : "f"(x));
    return u;
}

// ---------------- init + dtype detection -------------------------------------------
__global__ void k_init(const void* ei, const void* bt) {
    int i = blockIdx.x * blockDim.x + threadIdx.x;
    if (i < N_NODES) { g_dc[i] = 0ULL; g_cur[i] = 0; }
    if (i < N_GRAPHS * F)  g_pool[i] = 0.0f;
    if (i < N_GRAPHS)      g_cnt[i] = 0;
    if (i == 0) {
        const unsigned long long* p = (const unsigned long long*)ei;
        int is64 = 1;
        for (int k = 0; k < 512; k++)
            if (p[k] >= (1ULL << 32)) { is64 = 0; break; }
        g_ei64 = is64;
        const unsigned long long* q = (const unsigned long long*)bt;
        int b64 = 1;
        for (int k = 0; k < 512; k++)
            if (q[k] >= (1ULL << 32)) { b64 = 0; break; }
        g_b64 = b64;
    }
}

// ---------------- prep: ONE packed 64-bit atomic per edge --------------------------
__global__ void k_prep(const void* __restrict__ ei, const float* __restrict__ w) {
    int e = (blockIdx.x * blockDim.x + threadIdx.x) * 2;
    if (e >= N_EDGES) return;
    int is64 = g_ei64;
    int d0, d1;
    if (is64) {
        longlong2 dd = *(const longlong2*)((const long long*)ei + N_EDGES + e);
        d0 = clampi(dd.x, N_NODES); d1 = clampi(dd.y, N_NODES);
    } else {
        int2 dd = *(const int2*)((const int*)ei + N_EDGES + e);
        d0 = clampi(dd.x, N_NODES); d1 = clampi(dd.y, N_NODES);
    }
    float2 wv = *(const float2*)(w + e);
    unsigned long long p0 = (1ULL << 40) |
        (unsigned long long)(long long)(wv.x * FIXSCALE + 0.5f);
    unsigned long long p1 = (1ULL << 40) |
        (unsigned long long)(long long)(wv.y * FIXSCALE + 0.5f);
    atomicAdd(&g_dc[d0], p0);
    atomicAdd(&g_dc[d1], p1);
}

// ---------------- scan1: decode deg/cnt + dis/selfn/batch + block scan -------------
__global__ void k_scan1(const void* __restrict__ batch) {
    __shared__ int sm[256];
    int b = blockIdx.x, t = threadIdx.x;
    int i = b * 256 + t;

    int v = 0;
    if (i < N_NODES) {
        unsigned long long dc = g_dc[i];
        v = (int)(dc >> 40);                                   // incoming-edge count
        float dg = 1.0f + (float)(double)(dc & 0xFFFFFFFFFFULL) * (1.0f / FIXSCALE);
        float dis = dg > 0.0f ? rsqrtf(dg) : 0.0f;
        g_dis[i]   = dis;
        g_selfn[i] = dis * dis;
        int gph = load_idx(batch, i, g_b64, N_GRAPHS);
        g_gph[i] = gph;
        unsigned active = __activemask();
        unsigned mask = __match_any_sync(active, gph);
        int leader = __ffs(mask) - 1;
        if ((t & 31) == leader) atomicAdd(&g_cnt[gph], __popc(mask));
    }

    sm[t] = v; __syncthreads();
    for (int ofs = 1; ofs < 256; ofs <<= 1) {
        int add = (t >= ofs) ? sm[t - ofs] : 0;
        __syncthreads();
        sm[t] += add;
        __syncthreads();
    }
    if (i < N_NODES) g_off[i] = sm[t] - v;
    if (t == 255) g_part[b] = sm[255];
}

// ---------------- scan3: per-block prefix of partials + offset finalize ------------
__global__ void k_scan3() {
    __shared__ int sbase;
    int b = blockIdx.x, t = threadIdx.x;
    if (t < 32) {
        int s = 0;
        for (int j = t; j < b; j += 32) s += g_part[j];
#pragma unroll
        for (int o = 16; o > 0; o >>= 1) s += __shfl_down_sync(0xffffffff, s, o);
        if (t == 0) sbase = s;
    }
    __syncthreads();
    int i = b * 256 + t;
    if (i < N_NODES) g_off[i] += sbase;
    if (i == 0) g_off[N_NODES] = N_EDGES;
}

// ---------------- fill CSR (2 edges/thread, packed 8B entries) ---------------------
__global__ void k_fill(const void* __restrict__ ei, const float* __restrict__ w) {
    int e = (blockIdx.x * blockDim.x + threadIdx.x) * 2;
    if (e >= N_EDGES) return;
    int is64 = g_ei64;
    int s0, s1, d0, d1;
    if (is64) {
        longlong2 ss = *(const longlong2*)((const long long*)ei + e);
        longlong2 dd = *(const longlong2*)((const long long*)ei + N_EDGES + e);
        s0 = clampi(ss.x, N_NODES); s1 = clampi(ss.y, N_NODES);
        d0 = clampi(dd.x, N_NODES); d1 = clampi(dd.y, N_NODES);
    } else {
        int2 ss = *(const int2*)((const int*)ei + e);
        int2 dd = *(const int2*)((const int*)ei + N_EDGES + e);
        s0 = clampi(ss.x, N_NODES); s1 = clampi(ss.y, N_NODES);
        d0 = clampi(dd.x, N_NODES); d1 = clampi(dd.y, N_NODES);
    }
    float2 wv = *(const float2*)(w + e);
    int slot0 = g_off[d0] + atomicAdd(&g_cur[d0], 1);
    uint2 c0;
    c0.x = (unsigned)s0;
    c0.y = __float_as_uint(g_dis[s0] * wv.x * g_dis[d0]);
    g_csr[slot0] = c0;
    int slot1 = g_off[d1] + atomicAdd(&g_cur[d1], 1);
    uint2 c1;
    c1.x = (unsigned)s1;
    c1.y = __float_as_uint(g_dis[s1] * wv.y * g_dis[d1]);
    g_csr[slot1] = c1;
}

// ---------------- GEMM (tensor path): g_xwh = A @ W, tf32 mma, fp32 accum ----------
__global__ void k_gemm(const float* __restrict__ Aext, int asel,
                       const float* __restrict__ W) {
    __shared__ unsigned ws[96 * WS_PITCH];
    const float* A = (asel == 0) ? Aext : (asel == 1 ? g_hA : g_hB);

    int tid = threadIdx.x;
    for (int idx = tid; idx < 96 * 96; idx += 256) {
        int k = idx / 96, n = idx - k * 96;
        ws[k * WS_PITCH + n] = f2tf32(W[idx]);
    }
    __syncthreads();

    int lane = tid & 31, warp = tid >> 5;
    int r0 = blockIdx.x * 128 + warp * 16;
    int qr = lane >> 2;
    int qc = lane & 3;

    float acc[12][4];
#pragma unroll
    for (int n = 0; n < 12; n++)
#pragma unroll
        for (int j = 0; j < 4; j++) acc[n][j] = 0.0f;

    int row_lo = r0 + qr;
    int row_hi = row_lo + 8;
    int rl = row_lo < N_NODES ? row_lo : N_NODES - 1;
    int rh = row_hi < N_NODES ? row_hi : N_NODES - 1;

#pragma unroll
    for (int k0 = 0; k0 < 96; k0 += 8) {
        unsigned a0 = f2tf32(A[(size_t)rl * 96 + k0 + qc]);
        unsigned a1 = f2tf32(A[(size_t)rh * 96 + k0 + qc]);
        unsigned a2 = f2tf32(A[(size_t)rl * 96 + k0 + qc + 4]);
        unsigned a3 = f2tf32(A[(size_t)rh * 96 + k0 + qc + 4]);
#pragma unroll
        for (int n = 0; n < 12; n++) {
            unsigned b0 = ws[(k0 + qc) * WS_PITCH + n * 8 + qr];
            unsigned b1 = ws[(k0 + 4 + qc) * WS_PITCH + n * 8 + qr];
            asm volatile(
                "mma.sync.aligned.m16n8k8.row.col.f32.tf32.tf32.f32 "
                "{%0,%1,%2,%3}, {%4,%5,%6,%7}, {%8,%9}, {%0,%1,%2,%3};"
                : "+f"(acc[n][0]), "+f"(acc[n][1]), "+f"(acc[n][2]), "+f"(acc[n][3])
                : "r"(a0), "r"(a1), "r"(a2), "r"(a3), "r"(b0), "r"(b1));
        }
    }

    int colb = qc * 2;
#pragma unroll
    for (int n = 0; n < 12; n++) {
        int col = n * 8 + colb;
        if (row_lo < N_NODES)
            *(__half2*)&g_xwh[(size_t)row_lo * 96 + col] = __floats2half2_rn(acc[n][0], acc[n][1]);
        if (row_hi < N_NODES)
            *(__half2*)&g_xwh[(size_t)row_hi * 96 + col] = __floats2half2_rn(acc[n][2], acc[n][3]);
    }
}

// ---------------- fused gather: CSR aggregate + self-loop + bias (+relu) (+pool) ---
__global__ void k_gather(int osel, const float* __restrict__ bias, int relu, int do_pool) {
    int warp = (blockIdx.x * blockDim.x + threadIdx.x) >> 5;
    int lane = threadIdx.x & 31;
    if (warp >= N_NODES || lane >= NF4) return;
    float* out = buf_sel(osel);
    const uint2* __restrict__ xwu = (const uint2*)g_xwh;

    int beg = __ldg(&g_off[warp]), end = __ldg(&g_off[warp + 1]);
    float4 acc = make_float4(0.f, 0.f, 0.f, 0.f);
    int i = beg;
    for (; i + 3 < end; i += 4) {
        uint2 c0 = __ldg(&g_csr[i]);
        uint2 c1 = __ldg(&g_csr[i + 1]);
        uint2 c2 = __ldg(&g_csr[i + 2]);
        uint2 c3 = __ldg(&g_csr[i + 3]);
        float n0 = __uint_as_float(c0.y), n1 = __uint_as_float(c1.y);
        float n2 = __uint_as_float(c2.y), n3 = __uint_as_float(c3.y);
        uint2 u0 = xwu[(size_t)c0.x * NF4 + lane];
        uint2 u1 = xwu[(size_t)c1.x * NF4 + lane];
        uint2 u2 = xwu[(size_t)c2.x * NF4 + lane];
        uint2 u3 = xwu[(size_t)c3.x * NF4 + lane];
        float2 lo0 = __half22float2(*(__half2*)&u0.x), hi0 = __half22float2(*(__half2*)&u0.y);
        float2 lo1 = __half22float2(*(__half2*)&u1.x), hi1 = __half22float2(*(__half2*)&u1.y);
        float2 lo2 = __half22float2(*(__half2*)&u2.x), hi2 = __half22float2(*(__half2*)&u2.y);
        float2 lo3 = __half22float2(*(__half2*)&u3.x), hi3 = __half22float2(*(__half2*)&u3.y);
        acc.x = fmaf(n0, lo0.x, acc.x); acc.y = fmaf(n0, lo0.y, acc.y);
        acc.z = fmaf(n0, hi0.x, acc.z); acc.w = fmaf(n0, hi0.y, acc.w);
        acc.x = fmaf(n1, lo1.x, acc.x); acc.y = fmaf(n1, lo1.y, acc.y);
        acc.z = fmaf(n1, hi1.x, acc.z); acc.w = fmaf(n1, hi1.y, acc.w);
        acc.x = fmaf(n2, lo2.x, acc.x); acc.y = fmaf(n2, lo2.y, acc.y);
        acc.z = fmaf(n2, hi2.x, acc.z); acc.w = fmaf(n2, hi2.y, acc.w);
        acc.x = fmaf(n3, lo3.x, acc.x); acc.y = fmaf(n3, lo3.y, acc.y);
        acc.z = fmaf(n3, hi3.x, acc.z); acc.w = fmaf(n3, hi3.y, acc.w);
    }
    for (; i < end; i++) {
        uint2 c0 = __ldg(&g_csr[i]);
        float n0 = __uint_as_float(c0.y);
        uint2 u0 = xwu[(size_t)c0.x * NF4 + lane];
        float2 lo0 = __half22float2(*(__half2*)&u0.x), hi0 = __half22float2(*(__half2*)&u0.y);
        acc.x = fmaf(n0, lo0.x, acc.x); acc.y = fmaf(n0, lo0.y, acc.y);
        acc.z = fmaf(n0, hi0.x, acc.z); acc.w = fmaf(n0, hi0.y, acc.w);
    }
    {
        float sn = g_selfn[warp];
        uint2 u = xwu[(size_t)warp * NF4 + lane];
        float2 lo = __half22float2(*(__half2*)&u.x), hi = __half22float2(*(__half2*)&u.y);
        acc.x = fmaf(sn, lo.x, acc.x); acc.y = fmaf(sn, lo.y, acc.y);
        acc.z = fmaf(sn, hi.x, acc.z); acc.w = fmaf(sn, hi.y, acc.w);
    }
    float4 bv = ((const float4*)bias)[lane];
    acc.x += bv.x; acc.y += bv.y; acc.z += bv.z; acc.w += bv.w;
    if (relu) {
        acc.x = fmaxf(acc.x, 0.f); acc.y = fmaxf(acc.y, 0.f);
        acc.z = fmaxf(acc.z, 0.f); acc.w = fmaxf(acc.w, 0.f);
    }
    ((float4*)out)[(size_t)warp * NF4 + lane] = acc;

    if (do_pool) {
        int gph = g_gph[warp];
        float* pp = &g_pool[gph * F + lane * 4];
        atomicAdd(pp + 0, acc.x);
        atomicAdd(pp + 1, acc.y);
        atomicAdd(pp + 2, acc.z);
        atomicAdd(pp + 3, acc.w);
    }
}

// ---------------- head ------------------------------------------------------------
__global__ void k_final(const float* __restrict__ Wl, const float* __restrict__ bl,
                        float* __restrict__ out) {
    int t = blockIdx.x * blockDim.x + threadIdx.x;
    if (t >= N_GRAPHS * N_CLASSES) return;
    int gph = t / N_CLASSES;
    int c = t - gph * N_CLASSES;
    float inv = 1.0f / fmaxf((float)g_cnt[gph], 1.0f);
    float s = 0.0f;
#pragma unroll 8
    for (int k = 0; k < 96; k++)
        s = fmaf(g_pool[gph * 96 + k], Wl[k * N_CLASSES + c], s);
    out[t] = s * inv + bl[c];
}

// ===================================================================================
extern "C" void kernel_launch(void* const* d_in, const int* in_sizes, int n_in,
                              void* d_out, int out_size) {
    int ix = 0, iew = 1, iWl = 8, ibl = 9, iei = 10, ibatch = 11;
    int iW[3] = {2, 4, 6}, iB[3] = {3, 5, 7};
    {
        int tW[3], tB[3], nw = 0, nb = 0;
        int tx = -1, tew = -1, twl = -1, tbl = -1, tei = -1, tbt = -1;
        for (int i = 0; i < n_in; i++) {
            switch (in_sizes[i]) {
                case N_NODES * F:      tx  = i; break;
                case N_EDGES:          tew = i; break;
                case F * F:            if (nw < 3) tW[nw++] = i; break;
                case F:                if (nb < 3) tB[nb++] = i; break;
                case F * N_CLASSES:    twl = i; break;
                case N_CLASSES:        tbl = i; break;
                case 2 * N_EDGES:      tei = i; break;
                case N_NODES:          tbt = i; break;
                default: break;
            }
        }
        if (tx >= 0 && tew >= 0 && nw == 3 && nb == 3 && twl >= 0 && tbl >= 0 &&
            tei >= 0 && tbt >= 0) {
            ix = tx; iew = tew; iWl = twl; ibl = tbl; iei = tei; ibatch = tbt;
            for (int j = 0; j < 3; j++) { iW[j] = tW[j]; iB[j] = tB[j]; }
        }
    }

    const float* x     = (const float*)d_in[ix];
    const float* ew    = (const float*)d_in[iew];
    const float* W1    = (const float*)d_in[iW[0]];
    const float* b1    = (const float*)d_in[iB[0]];
    const float* W2    = (const float*)d_in[iW[1]];
    const float* b2    = (const float*)d_in[iB[1]];
    const float* W3    = (const float*)d_in[iW[2]];
    const float* b3    = (const float*)d_in[iB[2]];
    const float* Wl    = (const float*)d_in[iWl];
    const float* bl    = (const float*)d_in[ibl];
    const void*  ei    = d_in[iei];
    const void*  batch = d_in[ibatch];
    float* out = (float*)d_out;

    // side stream + events, created once (first call = correctness run, pre-capture)
    static cudaStream_t s2 = nullptr;
    static cudaEvent_t ev_fork = nullptr, ev_join = nullptr;
    if (s2 == nullptr) {
        cudaStreamCreateWithFlags(&s2, cudaStreamNonBlocking);
        cudaEventCreateWithFlags(&ev_fork, cudaEventDisableTiming);
        cudaEventCreateWithFlags(&ev_join, cudaEventDisableTiming);
    }

    const int T = 256;
    const int node_grid  = (N_NODES + T - 1) / T;
    const int edge2_grid = (N_EDGES / 2 + T - 1) / T;
    const int gemm_grid   = (N_NODES + 127) / 128;
    const int gather_grid = (N_NODES * 32 + T - 1) / T;

    // fork: GEMM1 (only needs x, W1) runs concurrently with the CSR build chain
    cudaEventRecord(ev_fork, 0);
    cudaStreamWaitEvent(s2, ev_fork, 0);
    k_gemm<<<gemm_grid, T, 0, s2>>>(x, 0, W1);
    cudaEventRecord(ev_join, s2);

    // prep chain on default stream
    k_init<<<node_grid, T>>>(ei, batch);
    k_prep<<<edge2_grid, T>>>(ei, ew);
    k_scan1<<<SCAN_NB, 256>>>(batch);
    k_scan3<<<SCAN_NB, 256>>>();
    k_fill<<<edge2_grid, T>>>(ei, ew);

    // join: gather1 needs CSR + GEMM1 output
    cudaStreamWaitEvent(0, ev_join, 0);
    k_gather<<<gather_grid, T>>>(1, b1, 1, 0);

    k_gemm<<<gemm_grid, T>>>(nullptr, 1, W2);
    k_gather<<<gather_grid, T>>>(2, b2, 1, 0);

    k_gemm<<<gemm_grid, T>>>(nullptr, 2, W3);
    k_gather<<<gather_grid, T>>>(1, b3, 0, 1);

    k_final<<<(N_GRAPHS * N_CLASSES + T - 1) / T, T>>>(Wl, bl, out);
}

// round 15
// speedup vs baseline: 1.1210x; 1.0182x over previous
#include <cuda_runtime.h>
#include <cuda_fp16.h>
#include <cstdint>

#define N_NODES   50000
#define N_EDGES   800000
#define F         96
#define NF4       (F / 4)          // 24 uint2 per fp16 node row
#define N_CLASSES 10
#define N_GRAPHS  512
#define NF        (N_NODES * F)
#define SCAN_NB   ((N_NODES + 255) / 256)   // 196
#define WS_PITCH  104
#define FIXSCALE  1048576.0f        // 2^20 fixed-point scale for weight sums

// ---------------- scratch (device globals; no allocations allowed) ----------------
__device__ unsigned long long g_dc[N_NODES];   // packed: count<<40 | fixed(deg sum)
__device__ float g_dis[N_NODES];
__device__ float g_selfn[N_NODES];
__device__ int   g_gph[N_NODES];
__device__ int   g_cur[N_NODES];
__device__ int   g_off[N_NODES + 1];           // block-local exclusive prefix
__device__ int   g_part[256];                  // per-block totals
__device__ int   g_base[256];                  // exclusive prefix of g_part
__device__ int   g_scan_done;
__device__ __align__(16) uint2  g_csr[N_EDGES];     // packed {src, norm-bits}
__device__ __align__(16) __half g_xwh[NF];
__device__ __align__(16) float  g_hA[NF];
__device__ __align__(16) float  g_hB[NF];
__device__ float g_pool[N_GRAPHS * F];
__device__ int   g_cnt[N_GRAPHS];
__device__ int   g_ei64, g_b64;

__device__ __forceinline__ float* buf_sel(int s) { return s == 1 ? g_hA : g_hB; }

__device__ __forceinline__ int clampi(long long v, int lim) {
    int r = (int)v;
    if (r < 0) r = 0;
    if (r >= lim) r = lim - 1;
    return r;
}

__device__ __forceinline__ int load_idx(const void* p, long long i, int is64, int lim) {
    long long v = is64 ? ((const long long*)p)[i] : (long long)((const int*)p)[i];
    return clampi(v, lim);
}

__device__ __forceinline__ unsigned f2tf32(float x) {
    unsigned u;
    asm("cvt.rna.tf32.f32 %0, %1;" : "=r"(u) : "f"(x));
    return u;
}

// ---------------- init + dtype detection -------------------------------------------
__global__ void k_init(const void* ei, const void* bt) {
    int i = blockIdx.x * blockDim.x + threadIdx.x;
    if (i < N_NODES) { g_dc[i] = 0ULL; g_cur[i] = 0; }
    if (i < N_GRAPHS * F)  g_pool[i] = 0.0f;
    if (i < N_GRAPHS)      g_cnt[i] = 0;
    if (i == 0) {
        g_scan_done = 0;
        const unsigned long long* p = (const unsigned long long*)ei;
        int is64 = 1;
        for (int k = 0; k < 512; k++)
            if (p[k] >= (1ULL << 32)) { is64 = 0; break; }
        g_ei64 = is64;
        const unsigned long long* q = (const unsigned long long*)bt;
        int b64 = 1;
        for (int k = 0; k < 512; k++)
            if (q[k] >= (1ULL << 32)) { b64 = 0; break; }
        g_b64 = b64;
    }
}

// ---------------- prep: ONE packed 64-bit atomic per edge --------------------------
__global__ void k_prep(const void* __restrict__ ei, const float* __restrict__ w) {
    cudaGridDependencySynchronize();
    int e = (blockIdx.x * blockDim.x + threadIdx.x) * 2;
    if (e >= N_EDGES) return;
    int is64 = g_ei64;
    int d0, d1;
    if (is64) {
        longlong2 dd = *(const longlong2*)((const long long*)ei + N_EDGES + e);
        d0 = clampi(dd.x, N_NODES); d1 = clampi(dd.y, N_NODES);
    } else {
        int2 dd = *(const int2*)((const int*)ei + N_EDGES + e);
        d0 = clampi(dd.x, N_NODES); d1 = clampi(dd.y, N_NODES);
    }
    float2 wv = *(const float2*)(w + e);
    unsigned long long p0 = (1ULL << 40) |
        (unsigned long long)(long long)(wv.x * FIXSCALE + 0.5f);
    unsigned long long p1 = (1ULL << 40) |
        (unsigned long long)(long long)(wv.y * FIXSCALE + 0.5f);
    atomicAdd(&g_dc[d0], p0);
    atomicAdd(&g_dc[d1], p1);
}

// ---------------- scan1: decode + dis/selfn/batch + block scan + base prefix -------
__global__ void k_scan1(const void* __restrict__ batch) {
    cudaGridDependencySynchronize();
    __shared__ int sm[256];
    __shared__ int s_last;
    int b = blockIdx.x, t = threadIdx.x;
    int i = b * 256 + t;

    int v = 0;
    if (i < N_NODES) {
        unsigned long long dc = g_dc[i];
        v = (int)(dc >> 40);
        float dg = 1.0f + (float)(double)(dc & 0xFFFFFFFFFFULL) * (1.0f / FIXSCALE);
        float dis = dg > 0.0f ? rsqrtf(dg) : 0.0f;
        g_dis[i]   = dis;
        g_selfn[i] = dis * dis;
        int gph = load_idx(batch, i, g_b64, N_GRAPHS);
        g_gph[i] = gph;
        unsigned active = __activemask();
        unsigned mask = __match_any_sync(active, gph);
        int leader = __ffs(mask) - 1;
        if ((t & 31) == leader) atomicAdd(&g_cnt[gph], __popc(mask));
    }

    sm[t] = v; __syncthreads();
    for (int ofs = 1; ofs < 256; ofs <<= 1) {
        int add = (t >= ofs) ? sm[t - ofs] : 0;
        __syncthreads();
        sm[t] += add;
        __syncthreads();
    }
    if (i < N_NODES) g_off[i] = sm[t] - v;       // block-local offsets
    if (t == 0) {
        g_part[b] = sm[255];
        __threadfence();                          // publish g_part before done-mark
        int d = atomicAdd(&g_scan_done, 1);
        s_last = (d == SCAN_NB - 1) ? 1 : 0;
    }
    __syncthreads();

    // last-finished block computes the 196-entry base prefix (replaces k_scan3)
    if (s_last) {
        __shared__ int sp[256];
        int v2 = (t < SCAN_NB) ? g_part[t] : 0;
        sp[t] = v2; __syncthreads();
        for (int ofs = 1; ofs < 256; ofs <<= 1) {
            int add = (t >= ofs) ? sp[t - ofs] : 0;
            __syncthreads();
            sp[t] += add;
            __syncthreads();
        }
        if (t < SCAN_NB) g_base[t] = sp[t] - v2;
        __syncthreads();
        if (t == 0) g_off[N_NODES] = N_EDGES - (sp[SCAN_NB - 1] - g_part[SCAN_NB - 1]);
    }
}

// ---------------- fill CSR (2 edges/thread, packed 8B entries) ---------------------
__global__ void k_fill(const void* __restrict__ ei, const float* __restrict__ w) {
    cudaGridDependencySynchronize();
    int e = (blockIdx.x * blockDim.x + threadIdx.x) * 2;
    if (e >= N_EDGES) return;
    int is64 = g_ei64;
    int s0, s1, d0, d1;
    if (is64) {
        longlong2 ss = *(const longlong2*)((const long long*)ei + e);
        longlong2 dd = *(const longlong2*)((const long long*)ei + N_EDGES + e);
        s0 = clampi(ss.x, N_NODES); s1 = clampi(ss.y, N_NODES);
        d0 = clampi(dd.x, N_NODES); d1 = clampi(dd.y, N_NODES);
    } else {
        int2 ss = *(const int2*)((const int*)ei + e);
        int2 dd = *(const int2*)((const int*)ei + N_EDGES + e);
        s0 = clampi(ss.x, N_NODES); s1 = clampi(ss.y, N_NODES);
        d0 = clampi(dd.x, N_NODES); d1 = clampi(dd.y, N_NODES);
    }
    float2 wv = *(const float2*)(w + e);
    int slot0 = g_off[d0] + __ldg(&g_base[d0 >> 8]) + atomicAdd(&g_cur[d0], 1);
    uint2 c0;
    c0.x = (unsigned)s0;
    c0.y = __float_as_uint(g_dis[s0] * wv.x * g_dis[d0]);
    g_csr[slot0] = c0;
    int slot1 = g_off[d1] + __ldg(&g_base[d1 >> 8]) + atomicAdd(&g_cur[d1], 1);
    uint2 c1;
    c1.x = (unsigned)s1;
    c1.y = __float_as_uint(g_dis[s1] * wv.y * g_dis[d1]);
    g_csr[slot1] = c1;
}

// ---------------- GEMM (tensor path): g_xwh = A @ W, tf32 mma, fp32 accum ----------
__global__ void k_gemm(const float* __restrict__ Aext, int asel,
                       const float* __restrict__ W) {
    __shared__ unsigned ws[96 * WS_PITCH];
    const float* A = (asel == 0) ? Aext : (asel == 1 ? g_hA : g_hB);

    // prologue: W smem load + tf32 convert (W is a kernel input; no dependency)
    int tid = threadIdx.x;
    for (int idx = tid; idx < 96 * 96; idx += 256) {
        int k = idx / 96, n = idx - k * 96;
        ws[k * WS_PITCH + n] = f2tf32(W[idx]);
    }
    __syncthreads();

    cudaGridDependencySynchronize();   // A (g_hA/g_hB) produced by prior gather

    int lane = tid & 31, warp = tid >> 5;
    int r0 = blockIdx.x * 128 + warp * 16;
    int qr = lane >> 2;
    int qc = lane & 3;

    float acc[12][4];
#pragma unroll
    for (int n = 0; n < 12; n++)
#pragma unroll
        for (int j = 0; j < 4; j++) acc[n][j] = 0.0f;

    int row_lo = r0 + qr;
    int row_hi = row_lo + 8;
    int rl = row_lo < N_NODES ? row_lo : N_NODES - 1;
    int rh = row_hi < N_NODES ? row_hi : N_NODES - 1;

#pragma unroll
    for (int k0 = 0; k0 < 96; k0 += 8) {
        unsigned a0 = f2tf32(A[(size_t)rl * 96 + k0 + qc]);
        unsigned a1 = f2tf32(A[(size_t)rh * 96 + k0 + qc]);
        unsigned a2 = f2tf32(A[(size_t)rl * 96 + k0 + qc + 4]);
        unsigned a3 = f2tf32(A[(size_t)rh * 96 + k0 + qc + 4]);
#pragma unroll
        for (int n = 0; n < 12; n++) {
            unsigned b0 = ws[(k0 + qc) * WS_PITCH + n * 8 + qr];
            unsigned b1 = ws[(k0 + 4 + qc) * WS_PITCH + n * 8 + qr];
            asm volatile(
                "mma.sync.aligned.m16n8k8.row.col.f32.tf32.tf32.f32 "
                "{%0,%1,%2,%3}, {%4,%5,%6,%7}, {%8,%9}, {%0,%1,%2,%3};"
                : "+f"(acc[n][0]), "+f"(acc[n][1]), "+f"(acc[n][2]), "+f"(acc[n][3])
                : "r"(a0), "r"(a1), "r"(a2), "r"(a3), "r"(b0), "r"(b1));
        }
    }

    int colb = qc * 2;
#pragma unroll
    for (int n = 0; n < 12; n++) {
        int col = n * 8 + colb;
        if (row_lo < N_NODES)
            *(__half2*)&g_xwh[(size_t)row_lo * 96 + col] = __floats2half2_rn(acc[n][0], acc[n][1]);
        if (row_hi < N_NODES)
            *(__half2*)&g_xwh[(size_t)row_hi * 96 + col] = __floats2half2_rn(acc[n][2], acc[n][3]);
    }
}

// ---------------- fused gather: CSR aggregate + self-loop + bias (+relu) (+pool) ---
__global__ void k_gather(int osel, const float* __restrict__ bias, int relu, int do_pool) {
    cudaGridDependencySynchronize();   // g_xwh produced by prior gemm
    int warp = (blockIdx.x * blockDim.x + threadIdx.x) >> 5;
    int lane = threadIdx.x & 31;
    if (warp >= N_NODES || lane >= NF4) return;
    float* out = buf_sel(osel);
    const uint2* __restrict__ xwu = (const uint2*)g_xwh;

    int beg = __ldg(&g_off[warp]) + __ldg(&g_base[warp >> 8]);
    int end = __ldg(&g_off[warp + 1]) + __ldg(&g_base[(warp + 1) >> 8]);
    float4 acc = make_float4(0.f, 0.f, 0.f, 0.f);
    int i = beg;
    for (; i + 3 < end; i += 4) {
        uint2 c0 = __ldg(&g_csr[i]);
        uint2 c1 = __ldg(&g_csr[i + 1]);
        uint2 c2 = __ldg(&g_csr[i + 2]);
        uint2 c3 = __ldg(&g_csr[i + 3]);
        float n0 = __uint_as_float(c0.y), n1 = __uint_as_float(c1.y);
        float n2 = __uint_as_float(c2.y), n3 = __uint_as_float(c3.y);
        uint2 u0 = xwu[(size_t)c0.x * NF4 + lane];
        uint2 u1 = xwu[(size_t)c1.x * NF4 + lane];
        uint2 u2 = xwu[(size_t)c2.x * NF4 + lane];
        uint2 u3 = xwu[(size_t)c3.x * NF4 + lane];
        float2 lo0 = __half22float2(*(__half2*)&u0.x), hi0 = __half22float2(*(__half2*)&u0.y);
        float2 lo1 = __half22float2(*(__half2*)&u1.x), hi1 = __half22float2(*(__half2*)&u1.y);
        float2 lo2 = __half22float2(*(__half2*)&u2.x), hi2 = __half22float2(*(__half2*)&u2.y);
        float2 lo3 = __half22float2(*(__half2*)&u3.x), hi3 = __half22float2(*(__half2*)&u3.y);
        acc.x = fmaf(n0, lo0.x, acc.x); acc.y = fmaf(n0, lo0.y, acc.y);
        acc.z = fmaf(n0, hi0.x, acc.z); acc.w = fmaf(n0, hi0.y, acc.w);
        acc.x = fmaf(n1, lo1.x, acc.x); acc.y = fmaf(n1, lo1.y, acc.y);
        acc.z = fmaf(n1, hi1.x, acc.z); acc.w = fmaf(n1, hi1.y, acc.w);
        acc.x = fmaf(n2, lo2.x, acc.x); acc.y = fmaf(n2, lo2.y, acc.y);
        acc.z = fmaf(n2, hi2.x, acc.z); acc.w = fmaf(n2, hi2.y, acc.w);
        acc.x = fmaf(n3, lo3.x, acc.x); acc.y = fmaf(n3, lo3.y, acc.y);
        acc.z = fmaf(n3, hi3.x, acc.z); acc.w = fmaf(n3, hi3.y, acc.w);
    }
    for (; i < end; i++) {
        uint2 c0 = __ldg(&g_csr[i]);
        float n0 = __uint_as_float(c0.y);
        uint2 u0 = xwu[(size_t)c0.x * NF4 + lane];
        float2 lo0 = __half22float2(*(__half2*)&u0.x), hi0 = __half22float2(*(__half2*)&u0.y);
        acc.x = fmaf(n0, lo0.x, acc.x); acc.y = fmaf(n0, lo0.y, acc.y);
        acc.z = fmaf(n0, hi0.x, acc.z); acc.w = fmaf(n0, hi0.y, acc.w);
    }
    {
        float sn = g_selfn[warp];
        uint2 u = xwu[(size_t)warp * NF4 + lane];
        float2 lo = __half22float2(*(__half2*)&u.x), hi = __half22float2(*(__half2*)&u.y);
        acc.x = fmaf(sn, lo.x, acc.x); acc.y = fmaf(sn, lo.y, acc.y);
        acc.z = fmaf(sn, hi.x, acc.z); acc.w = fmaf(sn, hi.y, acc.w);
    }
    float4 bv = ((const float4*)bias)[lane];
    acc.x += bv.x; acc.y += bv.y; acc.z += bv.z; acc.w += bv.w;
    if (relu) {
        acc.x = fmaxf(acc.x, 0.f); acc.y = fmaxf(acc.y, 0.f);
        acc.z = fmaxf(acc.z, 0.f); acc.w = fmaxf(acc.w, 0.f);
    }
    ((float4*)out)[(size_t)warp * NF4 + lane] = acc;

    if (do_pool) {
        int gph = g_gph[warp];
        float* pp = &g_pool[gph * F + lane * 4];
        atomicAdd(pp + 0, acc.x);
        atomicAdd(pp + 1, acc.y);
        atomicAdd(pp + 2, acc.z);
        atomicAdd(pp + 3, acc.w);
    }
}

// ---------------- head ------------------------------------------------------------
__global__ void k_final(const float* __restrict__ Wl, const float* __restrict__ bl,
                        float* __restrict__ out) {
    cudaGridDependencySynchronize();
    int t = blockIdx.x * blockDim.x + threadIdx.x;
    if (t >= N_GRAPHS * N_CLASSES) return;
    int gph = t / N_CLASSES;
    int c = t - gph * N_CLASSES;
    float inv = 1.0f / fmaxf((float)g_cnt[gph], 1.0f);
    float s = 0.0f;
#pragma unroll 8
    for (int k = 0; k < 96; k++)
        s = fmaf(g_pool[gph * 96 + k], Wl[k * N_CLASSES + c], s);
    out[t] = s * inv + bl[c];
}

// ---------------- PDL launch helper ------------------------------------------------
#define LAUNCH_PDL(kern, grid, blk, ...) do {                                   \
    cudaLaunchConfig_t _cfg = {};                                               \
    _cfg.gridDim = dim3(grid); _cfg.blockDim = dim3(blk);                       \
    _cfg.dynamicSmemBytes = 0; _cfg.stream = 0;                                 \
    cudaLaunchAttribute _at[1];                                                 \
    _at[0].id = cudaLaunchAttributeProgrammaticStreamSerialization;             \
    _at[0].val.programmaticStreamSerializationAllowed = 1;                      \
    _cfg.attrs = _at; _cfg.numAttrs = 1;                                        \
    cudaLaunchKernelEx(&_cfg, kern, __VA_ARGS__);                               \
} while (0)

// ===================================================================================
extern "C" void kernel_launch(void* const* d_in, const int* in_sizes, int n_in,
                              void* d_out, int out_size) {
    int ix = 0, iew = 1, iWl = 8, ibl = 9, iei = 10, ibatch = 11;
    int iW[3] = {2, 4, 6}, iB[3] = {3, 5, 7};
    {
        int tW[3], tB[3], nw = 0, nb = 0;
        int tx = -1, tew = -1, twl = -1, tbl = -1, tei = -1, tbt = -1;
        for (int i = 0; i < n_in; i++) {
            switch (in_sizes[i]) {
                case N_NODES * F:      tx  = i; break;
                case N_EDGES:          tew = i; break;
                case F * F:            if (nw < 3) tW[nw++] = i; break;
                case F:                if (nb < 3) tB[nb++] = i; break;
                case F * N_CLASSES:    twl = i; break;
                case N_CLASSES:        tbl = i; break;
                case 2 * N_EDGES:      tei = i; break;
                case N_NODES:          tbt = i; break;
                default: break;
            }
        }
        if (tx >= 0 && tew >= 0 && nw == 3 && nb == 3 && twl >= 0 && tbl >= 0 &&
            tei >= 0 && tbt >= 0) {
            ix = tx; iew = tew; iWl = twl; ibl = tbl; iei = tei; ibatch = tbt;
            for (int j = 0; j < 3; j++) { iW[j] = tW[j]; iB[j] = tB[j]; }
        }
    }

    const float* x     = (const float*)d_in[ix];
    const float* ew    = (const float*)d_in[iew];
    const float* W1    = (const float*)d_in[iW[0]];
    const float* b1    = (const float*)d_in[iB[0]];
    const float* W2    = (const float*)d_in[iW[1]];
    const float* b2    = (const float*)d_in[iB[1]];
    const float* W3    = (const float*)d_in[iW[2]];
    const float* b3    = (const float*)d_in[iB[2]];
    const float* Wl    = (const float*)d_in[iWl];
    const float* bl    = (const float*)d_in[ibl];
    const void*  ei    = d_in[iei];
    const void*  batch = d_in[ibatch];
    float* out = (float*)d_out;

    // side stream + events, created once (first call = correctness run, pre-capture)
    static cudaStream_t s2 = nullptr;
    static cudaEvent_t ev_fork = nullptr, ev_join = nullptr;
    if (s2 == nullptr) {
        cudaStreamCreateWithFlags(&s2, cudaStreamNonBlocking);
        cudaEventCreateWithFlags(&ev_fork, cudaEventDisableTiming);
        cudaEventCreateWithFlags(&ev_join, cudaEventDisableTiming);
    }

    const int T = 256;
    const int node_grid   = (N_NODES + T - 1) / T;
    const int edge2_grid  = (N_EDGES / 2 + T - 1) / T;
    const int gemm_grid   = (N_NODES + 127) / 128;
    const int gather_grid = (N_NODES * 32 + T - 1) / T;

    // fork: GEMM1 (only needs x, W1) runs concurrently with the CSR build chain
    cudaEventRecord(ev_fork, 0);
    cudaStreamWaitEvent(s2, ev_fork, 0);
    k_gemm<<<gemm_grid, T, 0, s2>>>(x, 0, W1);
    cudaEventRecord(ev_join, s2);

    // prep chain on default stream with PDL between stages
    k_init<<<node_grid, T>>>(ei, batch);
    LAUNCH_PDL(k_prep,  edge2_grid, T, ei, ew);
    LAUNCH_PDL(k_scan1, SCAN_NB,    T, batch);
    LAUNCH_PDL(k_fill,  edge2_grid, T, ei, ew);

    // join: gather1 needs CSR + GEMM1 output (event edge -> normal launch)
    cudaStreamWaitEvent(0, ev_join, 0);
    k_gather<<<gather_grid, T>>>(1, b1, 1, 0);

    LAUNCH_PDL(k_gemm,   gemm_grid,   T, (const float*)nullptr, 1, W2);
    LAUNCH_PDL(k_gather, gather_grid, T, 2, b2, 1, 0);

    LAUNCH_PDL(k_gemm,   gemm_grid,   T, (const float*)nullptr, 2, W3);
    LAUNCH_PDL(k_gather, gather_grid, T, 1, b3, 0, 1);

    LAUNCH_PDL(k_final, (N_GRAPHS * N_CLASSES + T - 1) / T, T, Wl, bl, out);
}